// round 4
// baseline (speedup 1.0000x reference)
#include <cuda_runtime.h>
#include <math.h>

#define CH 64
#define RESX 64
#define HW 4096
#define PWD 66
#define PP 4356
#define BATCH 4

// ---------------- static device scratch ----------------
__device__ float g_c0p[BATCH * CH * PP];      // padded, channel-major
__device__ float g_c1p[BATCH * CH * PP];
__device__ float g_f0pl[BATCH * PP * CH];     // padded, pixel-major
__device__ float g_delta[BATCH * CH * HW];
__device__ float g_s0[BATCH * PP];
__device__ float g_s1[BATCH * PP];
__device__ float g_inv0[BATCH * HW];
__device__ float g_inv1[BATCH * HW];
__device__ float g_D[(size_t)PP * PP];        // 75.9 MB, per-batch reuse (L2 resident)
__device__ float g_pval[16 * HW];
__device__ int   g_parg[16 * HW];
__device__ float g_Rstar[BATCH * HW];
__device__ int   g_Rarg[BATCH * HW];
__device__ float g_x1[BATCH * CH * HW];
__device__ float g_hb[BATCH * CH * HW];
__device__ float g_xl[BATCH * CH * HW];
__device__ float g_concat[BATCH * 2 * CH * HW];  // ch 0..63 = Delta_c_fea, 64..127 = T
__device__ float g_xs[BATCH * CH * HW];
__device__ float g_wt_head[CH * 25 * CH];
__device__ float g_wt_rb1[CH * 9 * CH];
__device__ float g_wt_rb2[CH * 9 * CH];
__device__ float g_wt_tail[CH * 25 * CH];
__device__ float g_wt_sq[2 * CH * 25 * CH];

// ---------------- utility kernels ----------------
__global__ void zero_kernel(float* __restrict__ p, int n) {
    int i = blockIdx.x * blockDim.x + threadIdx.x;
    if (i < n) p[i] = 0.f;
}

// src [64][cin][taps] (OIHW flat) -> dst [(ci*taps+t)*64 + co]
__global__ void wtrans_kernel(const float* __restrict__ src, float* __restrict__ dst,
                              int cin, int taps) {
    int n = 64 * cin * taps;
    int i = blockIdx.x * blockDim.x + threadIdx.x;
    if (i >= n) return;
    int co = i & 63;
    int rest = i >> 6;                 // ci*taps + t
    dst[i] = src[(size_t)co * cin * taps + rest];
}

// Build padded channel-major c0p/c1p, padded pixel-major f0pl, and delta image.
__global__ void __launch_bounds__(256) pack_kernel(const float* __restrict__ c0,
                                                   const float* __restrict__ c1,
                                                   const float* __restrict__ f0) {
    __shared__ float s0[64][65];
    __shared__ float s1[64][65];
    const int b = blockIdx.y, lr = blockIdx.x;
    const float* c0row = c0 + ((size_t)b * HW + (size_t)lr * 64) * CH;
    const float* c1row = c1 + ((size_t)b * HW + (size_t)lr * 64) * CH;
    const float* f0row = f0 + ((size_t)b * HW + (size_t)lr * 64) * CH;
    float* f0dst = g_f0pl + ((size_t)b * PP + (size_t)(lr + 1) * PWD + 1) * CH;
    for (int i = threadIdx.x; i < 64 * 64; i += 256) {
        int lc = i >> 6, ch = i & 63;
        s0[lc][ch] = c0row[i];
        s1[lc][ch] = c1row[i];
        f0dst[i] = f0row[i];
    }
    __syncthreads();
    const size_t pbase = (size_t)b * CH * PP;
    const int prow = (lr + 1) * PWD + 1;
    for (int i = threadIdx.x; i < 64 * 64; i += 256) {
        int ch = i >> 6, lc = i & 63;
        float v0 = s0[lc][ch], v1 = s1[lc][ch];
        g_c0p[pbase + (size_t)ch * PP + prow + lc] = v0;
        g_c1p[pbase + (size_t)ch * PP + prow + lc] = v1;
        g_delta[(size_t)b * CH * HW + (size_t)ch * HW + lr * 64 + lc] = v1 - v0;
    }
}

// per-pixel channel sum-of-squares into padded maps (warp per pixel)
__global__ void sumsq_kernel(const float* __restrict__ c0, const float* __restrict__ c1) {
    int gw = blockIdx.x * 8 + (threadIdx.x >> 5);
    int lane = threadIdx.x & 31;
    int b = gw >> 12, l = gw & 4095;
    const float* p0 = c0 + ((size_t)b * HW + l) * CH;
    const float* p1 = c1 + ((size_t)b * HW + l) * CH;
    float a = p0[lane], a2 = p0[lane + 32];
    float s0 = a * a + a2 * a2;
    float bb = p1[lane], b2 = p1[lane + 32];
    float s1 = bb * bb + b2 * b2;
#pragma unroll
    for (int off = 16; off; off >>= 1) {
        s0 += __shfl_down_sync(0xffffffffu, s0, off);
        s1 += __shfl_down_sync(0xffffffffu, s1, off);
    }
    if (lane == 0) {
        int pr = ((l >> 6) + 1) * PWD + (l & 63) + 1;
        g_s0[b * PP + pr] = s0;
        g_s1[b * PP + pr] = s1;
    }
}

__global__ void norminv_kernel() {
    int i = blockIdx.x * 256 + threadIdx.x;
    if (i >= BATCH * HW) return;
    int b = i >> 12, l = i & 4095;
    int lp = (l >> 6) * PWD + (l & 63);
    float t0 = 0.f, t1 = 0.f;
#pragma unroll
    for (int ki = 0; ki < 3; ki++)
#pragma unroll
        for (int kj = 0; kj < 3; kj++) {
            int p = lp + ki * PWD + kj;
            t0 += g_s0[b * PP + p];
            t1 += g_s1[b * PP + p];
        }
    g_inv0[i] = 1.f / fmaxf(sqrtf(t0), 1e-12f);
    g_inv1[i] = 1.f / fmaxf(sqrtf(t1), 1e-12f);
}

// D = A^T B per batch; A=c0p[b] [64][PP], B=c1p[b] [64][PP]; 64x64 tiles, K=64.
__global__ void __launch_bounds__(256) dgemm_kernel(int b) {
    __shared__ __align__(16) float As[64][64];
    __shared__ __align__(16) float Bs[64][64];
    const float* A = g_c0p + (size_t)b * CH * PP;
    const float* Bm = g_c1p + (size_t)b * CH * PP;
    const int p0 = blockIdx.y * 64, q0 = blockIdx.x * 64;
    for (int i = threadIdx.x; i < 64 * 64; i += 256) {
        int k = i >> 6, x = i & 63;
        int p = p0 + x;
        As[k][x] = (p < PP) ? A[(size_t)k * PP + p] : 0.f;
        int q = q0 + x;
        Bs[k][x] = (q < PP) ? Bm[(size_t)k * PP + q] : 0.f;
    }
    __syncthreads();
    const int ty = threadIdx.x >> 4, tx = threadIdx.x & 15;
    float acc[4][4] = {};
#pragma unroll
    for (int k = 0; k < 64; k++) {
        float4 av = *(const float4*)&As[k][ty << 2];
        float4 bv = *(const float4*)&Bs[k][tx << 2];
        float a4[4] = {av.x, av.y, av.z, av.w};
        float b4[4] = {bv.x, bv.y, bv.z, bv.w};
#pragma unroll
        for (int i = 0; i < 4; i++)
#pragma unroll
            for (int j = 0; j < 4; j++) acc[i][j] += a4[i] * b4[j];
    }
    const int q = q0 + (tx << 2);
#pragma unroll
    for (int i = 0; i < 4; i++) {
        int p = p0 + (ty << 2) + i;
        if (p < PP && q < PP)
            *(float4*)&g_D[(size_t)p * PP + q] =
                make_float4(acc[i][0], acc[i][1], acc[i][2], acc[i][3]);
    }
}

// Fused 9-point assembly + normalize-by-inv0 + max/argmax over l-chunks.
__global__ void __launch_bounds__(256) assemble_kernel(int b) {
    const int mi = threadIdx.x & 63;
    const int sub = threadIdx.x >> 6;
    const int mr = blockIdx.x;
    const int m = mr * 64 + mi;
    const int mp = mr * PWD + mi;
    const int chunk = blockIdx.y * 4 + sub;
    const int l0 = chunk * 256;
    const float* inv0 = g_inv0 + b * HW;
    float best = -1e30f;
    int barg = 0;
    for (int li = 0; li < 256; li++) {
        int l = l0 + li;
        int lr = l >> 6, lc = l & 63;
        size_t lp = (size_t)lr * PWD + lc;
        float dot = 0.f;
#pragma unroll
        for (int ki = 0; ki < 3; ki++)
#pragma unroll
            for (int kj = 0; kj < 3; kj++) {
                size_t o = (size_t)ki * PWD + kj;
                dot += __ldg(&g_D[(lp + o) * PP + mp + o]);
            }
        float v = dot * __ldg(&inv0[l]);
        if (v > best) { best = v; barg = l; }
    }
    g_pval[chunk * HW + m] = best;
    g_parg[chunk * HW + m] = barg;
}

__global__ void merge_kernel(int b) {
    int m = blockIdx.x * 256 + threadIdx.x;
    if (m >= HW) return;
    float best = -1e30f;
    int barg = 0;
#pragma unroll
    for (int c = 0; c < 16; c++) {
        float v = g_pval[c * HW + m];
        if (v > best) { best = v; barg = g_parg[c * HW + m]; }
    }
    g_Rstar[b * HW + m] = best * g_inv1[b * HW + m];
    g_Rarg[b * HW + m] = barg;
}

// T = fold3(gather(f0u, R_arg)) / 9 into g_concat channels [64,128)
__global__ void gather_kernel() {
    int gw = blockIdx.x * 8 + (threadIdx.x >> 5);
    int lane = threadIdx.x & 31;
    int b = gw >> 12, l = gw & 4095;
    int h = l >> 6, w = l & 63;
    const float* f0b = g_f0pl + (size_t)b * PP * CH;
    const int* argb = g_Rarg + b * HW;
    float acc0 = 0.f, acc1 = 0.f;
#pragma unroll
    for (int ki = 0; ki < 3; ki++) {
        int y = h + 1 - ki;
        if ((unsigned)y >= (unsigned)RESX) continue;
#pragma unroll
        for (int kj = 0; kj < 3; kj++) {
            int x = w + 1 - kj;
            if ((unsigned)x >= (unsigned)RESX) continue;
            int a = argb[y * RESX + x];
            int ar = a >> 6, ac = a & 63;
            const float* src = f0b + ((size_t)(ar + ki) * PWD + ac + kj) * CH;
            acc0 += src[lane];
            acc1 += src[lane + 32];
        }
    }
    float* Tout = g_concat + ((size_t)b * 2 * CH + CH) * HW + l;
    Tout[(size_t)lane * HW] = acc0 * (1.f / 9.f);
    Tout[(size_t)(lane + 32) * HW] = acc1 * (1.f / 9.f);
}

// Direct conv, 64 out channels, tile = 1 row (64px) x 64 cout; thread = 2px x 8cout.
template <int KS, int CIN, bool RELU, bool HASRES>
__global__ void __launch_bounds__(256) conv_kernel(const float* __restrict__ in, int inBS,
                                                   const float* __restrict__ wt,
                                                   const float* __restrict__ bias,
                                                   const float* __restrict__ res,
                                                   float* __restrict__ out, int outBS) {
    constexpr int PAD = KS / 2;
    constexpr int IW = 64 + 2 * PAD;
    constexpr int K2 = KS * KS;
    __shared__ __align__(16) float sw[K2 * 64];      // declared FIRST + aligned (float4 reads)
    __shared__ __align__(16) float sin_[KS][IW];
    const int b = blockIdx.y;
    const int row = blockIdx.x;
    const int t = threadIdx.x;
    const int og = t & 7, pg = t >> 3;
    const int c0 = pg * 2;
    float acc[2][8];
#pragma unroll
    for (int i = 0; i < 2; i++)
#pragma unroll
        for (int j = 0; j < 8; j++) acc[i][j] = 0.f;

    const float* inb = in + (size_t)b * inBS;
    for (int ci = 0; ci < CIN; ci++) {
        for (int i = t; i < K2 * 64; i += 256) sw[i] = wt[(size_t)ci * K2 * 64 + i];
        for (int i = t; i < KS * IW; i += 256) {
            int r = i / IW, c = i % IW;
            int y = row - PAD + r, x = c - PAD;
            float v = 0.f;
            if ((unsigned)y < 64u && (unsigned)x < 64u)
                v = inb[(size_t)ci * HW + y * 64 + x];
            sin_[r][c] = v;
        }
        __syncthreads();
#pragma unroll
        for (int ky = 0; ky < KS; ky++) {
#pragma unroll
            for (int kx = 0; kx < KS; kx++) {
                float i0 = sin_[ky][c0 + kx];
                float i1 = sin_[ky][c0 + kx + 1];
                const float* wp = &sw[(ky * KS + kx) * 64 + og * 8];
                float4 wa = *(const float4*)wp;
                float4 wb = *(const float4*)(wp + 4);
                acc[0][0] += i0 * wa.x; acc[1][0] += i1 * wa.x;
                acc[0][1] += i0 * wa.y; acc[1][1] += i1 * wa.y;
                acc[0][2] += i0 * wa.z; acc[1][2] += i1 * wa.z;
                acc[0][3] += i0 * wa.w; acc[1][3] += i1 * wa.w;
                acc[0][4] += i0 * wb.x; acc[1][4] += i1 * wb.x;
                acc[0][5] += i0 * wb.y; acc[1][5] += i1 * wb.y;
                acc[0][6] += i0 * wb.z; acc[1][6] += i1 * wb.z;
                acc[0][7] += i0 * wb.w; acc[1][7] += i1 * wb.w;
            }
        }
        __syncthreads();
    }
    float* outb = out + (size_t)b * outBS;
    const float* resb = res + (size_t)b * CH * HW;
#pragma unroll
    for (int j = 0; j < 8; j++) {
        int co = og * 8 + j;
        float bv = bias[co];
#pragma unroll
        for (int i = 0; i < 2; i++) {
            float v = acc[i][j] + bv;
            if (RELU) v = fmaxf(v, 0.f);
            size_t idx = (size_t)co * HW + row * 64 + c0 + i;
            if (HASRES) v += resb[idx];
            outb[idx] = v;
        }
    }
}

// out[b][l][c] = fea[b][c][l] + xs[b][c][l] * S[b][l]  (transpose via smem)
__global__ void __launch_bounds__(256) finalize_kernel(float* __restrict__ out) {
    __shared__ float s[64][65];
    const int b = blockIdx.y, lr = blockIdx.x;
    const float* fea = g_concat + (size_t)b * 2 * CH * HW;
    const float* xs = g_xs + (size_t)b * CH * HW;
    const float* Sv = g_Rstar + b * HW + lr * 64;
    for (int i = threadIdx.x; i < 64 * 64; i += 256) {
        int ch = i >> 6, lc = i & 63;
        size_t idx = (size_t)ch * HW + lr * 64 + lc;
        s[lc][ch] = fea[idx] + xs[idx] * Sv[lc];
    }
    __syncthreads();
    float* ob = out + ((size_t)b * HW + (size_t)lr * 64) * 64;
    for (int i = threadIdx.x; i < 64 * 64; i += 256) ob[i] = s[i >> 6][i & 63];
}

// ---------------- host ----------------
static inline float* symaddr(const void* sym) {
    void* p = nullptr;
    cudaGetSymbolAddress(&p, sym);
    return (float*)p;
}

extern "C" void kernel_launch(void* const* d_in, const int* in_sizes, int n_in,
                              void* d_out, int out_size) {
    const float* c0 = (const float*)d_in[0];
    const float* f0 = (const float*)d_in[1];
    const float* c1 = (const float*)d_in[2];
    const float* head_w = (const float*)d_in[3];
    const float* head_b = (const float*)d_in[4];
    const float* rb_w1 = (const float*)d_in[5];
    const float* rb_b1 = (const float*)d_in[6];
    const float* rb_w2 = (const float*)d_in[7];
    const float* rb_b2 = (const float*)d_in[8];
    const float* tail_w = (const float*)d_in[9];
    const float* tail_b = (const float*)d_in[10];
    const float* sq_w = (const float*)d_in[11];
    const float* sq_b = (const float*)d_in[12];
    float* out = (float*)d_out;

    float* p_c0p = symaddr(g_c0p);
    float* p_c1p = symaddr(g_c1p);
    float* p_f0pl = symaddr(g_f0pl);
    float* p_s0 = symaddr(g_s0);
    float* p_s1 = symaddr(g_s1);
    float* p_delta = symaddr(g_delta);
    float* p_x1 = symaddr(g_x1);
    float* p_hb = symaddr(g_hb);
    float* p_xl = symaddr(g_xl);
    float* p_concat = symaddr(g_concat);
    float* p_xs = symaddr(g_xs);
    float* p_wh = symaddr(g_wt_head);
    float* p_w1 = symaddr(g_wt_rb1);
    float* p_w2 = symaddr(g_wt_rb2);
    float* p_wt = symaddr(g_wt_tail);
    float* p_ws = symaddr(g_wt_sq);

    const int NPAD = BATCH * CH * PP;  // == BATCH*PP*CH
    zero_kernel<<<(NPAD + 255) / 256, 256>>>(p_c0p, NPAD);
    zero_kernel<<<(NPAD + 255) / 256, 256>>>(p_c1p, NPAD);
    zero_kernel<<<(NPAD + 255) / 256, 256>>>(p_f0pl, NPAD);
    zero_kernel<<<(BATCH * PP + 255) / 256, 256>>>(p_s0, BATCH * PP);
    zero_kernel<<<(BATCH * PP + 255) / 256, 256>>>(p_s1, BATCH * PP);

    wtrans_kernel<<<(64 * 64 * 25 + 255) / 256, 256>>>(head_w, p_wh, 64, 25);
    wtrans_kernel<<<(64 * 64 * 9 + 255) / 256, 256>>>(rb_w1 + 3 * 64 * 64 * 9, p_w1, 64, 9);
    wtrans_kernel<<<(64 * 64 * 9 + 255) / 256, 256>>>(rb_w2 + 3 * 64 * 64 * 9, p_w2, 64, 9);
    wtrans_kernel<<<(64 * 64 * 25 + 255) / 256, 256>>>(tail_w, p_wt, 64, 25);
    wtrans_kernel<<<(64 * 128 * 25 + 255) / 256, 256>>>(sq_w, p_ws, 128, 25);

    pack_kernel<<<dim3(64, BATCH), 256>>>(c0, c1, f0);
    sumsq_kernel<<<BATCH * HW / 8, 256>>>(c0, c1);
    norminv_kernel<<<BATCH * HW / 256, 256>>>();

    for (int b = 0; b < BATCH; b++) {
        dgemm_kernel<<<dim3(69, 69), 256>>>(b);
        assemble_kernel<<<dim3(64, 4), 256>>>(b);
        merge_kernel<<<HW / 256, 256>>>(b);
    }
    gather_kernel<<<BATCH * HW / 8, 256>>>();

    // conv stack (only residual block 3 is live in the reference)
    conv_kernel<5, 64, false, false><<<dim3(64, BATCH), 256>>>(
        p_delta, CH * HW, p_wh, head_b, nullptr, p_x1, CH * HW);
    conv_kernel<3, 64, true, false><<<dim3(64, BATCH), 256>>>(
        p_x1, CH * HW, p_w1, rb_b1 + 3 * 64, nullptr, p_hb, CH * HW);
    conv_kernel<3, 64, false, true><<<dim3(64, BATCH), 256>>>(
        p_hb, CH * HW, p_w2, rb_b2 + 3 * 64, p_x1, p_xl, CH * HW);
    conv_kernel<5, 64, false, true><<<dim3(64, BATCH), 256>>>(
        p_xl, CH * HW, p_wt, tail_b, p_x1, p_concat, 2 * CH * HW);  // Delta_c_fea -> concat[0:64]
    conv_kernel<5, 128, false, false><<<dim3(64, BATCH), 256>>>(
        p_concat, 2 * CH * HW, p_ws, sq_b, nullptr, p_xs, CH * HW);

    finalize_kernel<<<dim3(64, BATCH), 256>>>(out);
}

// round 5
// speedup vs baseline: 1.0078x; 1.0078x over previous
#include <cuda_runtime.h>
#include <math.h>

#define CH 64
#define RESX 64
#define HW 4096
#define PWD 66
#define PP 4356
#define BATCH 4

// ---------------- f32x2 packed-FMA helpers (sm_103a) ----------------
__device__ __forceinline__ unsigned long long pack2(float lo, float hi) {
    unsigned long long r;
    asm("mov.b64 %0, {%1, %2};" : "=l"(r) : "f"(lo), "f"(hi));
    return r;
}
__device__ __forceinline__ void ffma2(unsigned long long& d, unsigned long long a,
                                      unsigned long long b) {
    asm("fma.rn.f32x2 %0, %1, %2, %0;" : "+l"(d) : "l"(a), "l"(b));
}
__device__ __forceinline__ float2 unpack2(unsigned long long v) {
    float2 r;
    asm("mov.b64 {%0, %1}, %2;" : "=f"(r.x), "=f"(r.y) : "l"(v));
    return r;
}

// ---------------- static device scratch ----------------
__device__ float g_c0p[BATCH * CH * PP];      // padded, channel-major
__device__ float g_c1p[BATCH * CH * PP];
__device__ float g_f0pl[BATCH * PP * CH];     // padded, pixel-major
__device__ float g_delta[BATCH * CH * HW];
__device__ float g_s0[BATCH * PP];
__device__ float g_s1[BATCH * PP];
__device__ float g_inv0[BATCH * HW];
__device__ float g_inv1[BATCH * HW];
__device__ float g_D[(size_t)PP * PP];        // 75.9 MB, per-batch reuse (L2 resident)
__device__ float g_pval[16 * HW];
__device__ int   g_parg[16 * HW];
__device__ float g_Rstar[BATCH * HW];
__device__ int   g_Rarg[BATCH * HW];
__device__ float g_x1[BATCH * CH * HW];
__device__ float g_hb[BATCH * CH * HW];
__device__ float g_xl[BATCH * CH * HW];
__device__ float g_concat[BATCH * 2 * CH * HW];  // ch 0..63 = Delta_c_fea, 64..127 = T
__device__ float g_xs[BATCH * CH * HW];
__device__ float g_wt_head[CH * 25 * CH];
__device__ float g_wt_rb1[CH * 9 * CH];
__device__ float g_wt_rb2[CH * 9 * CH];
__device__ float g_wt_tail[CH * 25 * CH];
__device__ float g_wt_sq[2 * CH * 25 * CH];

// ---------------- fused utility kernels ----------------
__global__ void zero_all_kernel() {
    int i = blockIdx.x * 256 + threadIdx.x;
    const int N1 = BATCH * CH * PP;
    if (i < N1) {
        g_c0p[i] = 0.f;
        g_c1p[i] = 0.f;
        g_f0pl[i] = 0.f;
    }
    if (i < BATCH * PP) {
        g_s0[i] = 0.f;
        g_s1[i] = 0.f;
    }
}

// transpose all 5 weight tensors: [64][cin][taps] -> [(ci*taps+t)*64 + co]
__global__ void wtrans_all_kernel(const float* __restrict__ hw, const float* __restrict__ w1,
                                  const float* __restrict__ w2, const float* __restrict__ tw,
                                  const float* __restrict__ sw) {
    int i = blockIdx.x * 256 + threadIdx.x;
    const float* src;
    float* dst;
    int j;
    if (i < 102400) { src = hw; dst = g_wt_head; j = i; }
    else if (i < 139264) { src = w1; dst = g_wt_rb1; j = i - 102400; }
    else if (i < 176128) { src = w2; dst = g_wt_rb2; j = i - 139264; }
    else if (i < 278528) { src = tw; dst = g_wt_tail; j = i - 176128; }
    else if (i < 483328) { src = sw; dst = g_wt_sq; j = i - 278528; }
    else return;
    int co = j & 63;
    int rest = j >> 6;  // ci*taps + t
    int n = (i < 102400) ? 1600 : (i < 176128) ? 576 : (i < 278528) ? 1600 : 3200;
    dst[j] = src[(size_t)co * n + rest];
}

// Build padded channel-major c0p/c1p, padded pixel-major f0pl, and delta image.
__global__ void __launch_bounds__(256) pack_kernel(const float* __restrict__ c0,
                                                   const float* __restrict__ c1,
                                                   const float* __restrict__ f0) {
    __shared__ float s0[64][65];
    __shared__ float s1[64][65];
    const int b = blockIdx.y, lr = blockIdx.x;
    const float* c0row = c0 + ((size_t)b * HW + (size_t)lr * 64) * CH;
    const float* c1row = c1 + ((size_t)b * HW + (size_t)lr * 64) * CH;
    const float* f0row = f0 + ((size_t)b * HW + (size_t)lr * 64) * CH;
    float* f0dst = g_f0pl + ((size_t)b * PP + (size_t)(lr + 1) * PWD + 1) * CH;
    for (int i = threadIdx.x; i < 64 * 64; i += 256) {
        int lc = i >> 6, ch = i & 63;
        s0[lc][ch] = c0row[i];
        s1[lc][ch] = c1row[i];
        f0dst[i] = f0row[i];
    }
    __syncthreads();
    const size_t pbase = (size_t)b * CH * PP;
    const int prow = (lr + 1) * PWD + 1;
    for (int i = threadIdx.x; i < 64 * 64; i += 256) {
        int ch = i >> 6, lc = i & 63;
        float v0 = s0[lc][ch], v1 = s1[lc][ch];
        g_c0p[pbase + (size_t)ch * PP + prow + lc] = v0;
        g_c1p[pbase + (size_t)ch * PP + prow + lc] = v1;
        g_delta[(size_t)b * CH * HW + (size_t)ch * HW + lr * 64 + lc] = v1 - v0;
    }
}

// per-pixel channel sum-of-squares into padded maps (warp per pixel)
__global__ void sumsq_kernel(const float* __restrict__ c0, const float* __restrict__ c1) {
    int gw = blockIdx.x * 8 + (threadIdx.x >> 5);
    int lane = threadIdx.x & 31;
    int b = gw >> 12, l = gw & 4095;
    const float* p0 = c0 + ((size_t)b * HW + l) * CH;
    const float* p1 = c1 + ((size_t)b * HW + l) * CH;
    float a = p0[lane], a2 = p0[lane + 32];
    float s0 = a * a + a2 * a2;
    float bb = p1[lane], b2 = p1[lane + 32];
    float s1 = bb * bb + b2 * b2;
#pragma unroll
    for (int off = 16; off; off >>= 1) {
        s0 += __shfl_down_sync(0xffffffffu, s0, off);
        s1 += __shfl_down_sync(0xffffffffu, s1, off);
    }
    if (lane == 0) {
        int pr = ((l >> 6) + 1) * PWD + (l & 63) + 1;
        g_s0[b * PP + pr] = s0;
        g_s1[b * PP + pr] = s1;
    }
}

__global__ void norminv_kernel() {
    int i = blockIdx.x * 256 + threadIdx.x;
    if (i >= BATCH * HW) return;
    int b = i >> 12, l = i & 4095;
    int lp = (l >> 6) * PWD + (l & 63);
    float t0 = 0.f, t1 = 0.f;
#pragma unroll
    for (int ki = 0; ki < 3; ki++)
#pragma unroll
        for (int kj = 0; kj < 3; kj++) {
            int p = lp + ki * PWD + kj;
            t0 += g_s0[b * PP + p];
            t1 += g_s1[b * PP + p];
        }
    g_inv0[i] = 1.f / fmaxf(sqrtf(t0), 1e-12f);
    g_inv1[i] = 1.f / fmaxf(sqrtf(t1), 1e-12f);
}

// D = A^T B per batch; A=c0p[b] [64][PP], B=c1p[b] [64][PP].
// 128x128 tile, 256 threads, thread = 8p x 8q, f32x2 paired over q, K=64 single stage.
__global__ void __launch_bounds__(256) dgemm_kernel(int b) {
    extern __shared__ __align__(16) float sm[];
    float* As = sm;               // [64][128] k-major
    float* Bs = sm + 64 * 128;    // [64][128]
    const float* A = g_c0p + (size_t)b * CH * PP;
    const float* Bm = g_c1p + (size_t)b * CH * PP;
    const int p0 = blockIdx.y * 128, q0 = blockIdx.x * 128;
    for (int i = threadIdx.x * 4; i < 64 * 128; i += 1024) {
        int k = i >> 7, x = i & 127;
        float4 va = make_float4(0.f, 0.f, 0.f, 0.f);
        float4 vb = va;
        if (p0 + x < PP) va = *(const float4*)&A[(size_t)k * PP + p0 + x];
        if (q0 + x < PP) vb = *(const float4*)&Bm[(size_t)k * PP + q0 + x];
        *(float4*)&As[k * 128 + x] = va;
        *(float4*)&Bs[k * 128 + x] = vb;
    }
    __syncthreads();
    const int ty = threadIdx.x >> 4, tx = threadIdx.x & 15;
    unsigned long long acc[8][4];
#pragma unroll
    for (int p = 0; p < 8; p++)
#pragma unroll
        for (int j = 0; j < 4; j++) acc[p][j] = 0ULL;
    const float* ap = &As[ty * 8];
    const float* bp = &Bs[tx * 8];
#pragma unroll 16
    for (int k = 0; k < 64; k++) {
        float4 a0 = *(const float4*)(ap + k * 128);
        float4 a1 = *(const float4*)(ap + k * 128 + 4);
        ulonglong2 b01 = *(const ulonglong2*)(bp + k * 128);
        ulonglong2 b23 = *(const ulonglong2*)(bp + k * 128 + 4);
        float av[8] = {a0.x, a0.y, a0.z, a0.w, a1.x, a1.y, a1.z, a1.w};
#pragma unroll
        for (int p = 0; p < 8; p++) {
            unsigned long long ad = pack2(av[p], av[p]);
            ffma2(acc[p][0], ad, b01.x);
            ffma2(acc[p][1], ad, b01.y);
            ffma2(acc[p][2], ad, b23.x);
            ffma2(acc[p][3], ad, b23.y);
        }
    }
    const int qb = q0 + tx * 8;
#pragma unroll
    for (int p = 0; p < 8; p++) {
        int gp = p0 + ty * 8 + p;
        if (gp < PP) {
            float* drow = &g_D[(size_t)gp * PP];
            if (qb + 3 < PP)
                *(ulonglong2*)&drow[qb] = make_ulonglong2(acc[p][0], acc[p][1]);
            if (qb + 7 < PP)
                *(ulonglong2*)&drow[qb + 4] = make_ulonglong2(acc[p][2], acc[p][3]);
        }
    }
}

// Fused 9-point assembly + normalize-by-inv0 + max/argmax over l-chunks.
__global__ void __launch_bounds__(256) assemble_kernel(int b) {
    const int mi = threadIdx.x & 63;
    const int sub = threadIdx.x >> 6;
    const int mr = blockIdx.x;
    const int m = mr * 64 + mi;
    const int mp = mr * PWD + mi;
    const int chunk = blockIdx.y * 4 + sub;
    const int l0 = chunk * 256;
    const float* inv0 = g_inv0 + b * HW;
    float best = -1e30f;
    int barg = 0;
    for (int li = 0; li < 256; li++) {
        int l = l0 + li;
        int lr = l >> 6, lc = l & 63;
        size_t lp = (size_t)lr * PWD + lc;
        float dot = 0.f;
#pragma unroll
        for (int ki = 0; ki < 3; ki++)
#pragma unroll
            for (int kj = 0; kj < 3; kj++) {
                size_t o = (size_t)ki * PWD + kj;
                dot += __ldg(&g_D[(lp + o) * PP + mp + o]);
            }
        float v = dot * __ldg(&inv0[l]);
        if (v > best) { best = v; barg = l; }
    }
    g_pval[chunk * HW + m] = best;
    g_parg[chunk * HW + m] = barg;
}

__global__ void merge_kernel(int b) {
    int m = blockIdx.x * 256 + threadIdx.x;
    if (m >= HW) return;
    float best = -1e30f;
    int barg = 0;
#pragma unroll
    for (int c = 0; c < 16; c++) {
        float v = g_pval[c * HW + m];
        if (v > best) { best = v; barg = g_parg[c * HW + m]; }
    }
    g_Rstar[b * HW + m] = best * g_inv1[b * HW + m];
    g_Rarg[b * HW + m] = barg;
}

// T = fold3(gather(f0u, R_arg)) / 9 into g_concat channels [64,128)
__global__ void gather_kernel() {
    int gw = blockIdx.x * 8 + (threadIdx.x >> 5);
    int lane = threadIdx.x & 31;
    int b = gw >> 12, l = gw & 4095;
    int h = l >> 6, w = l & 63;
    const float* f0b = g_f0pl + (size_t)b * PP * CH;
    const int* argb = g_Rarg + b * HW;
    float acc0 = 0.f, acc1 = 0.f;
#pragma unroll
    for (int ki = 0; ki < 3; ki++) {
        int y = h + 1 - ki;
        if ((unsigned)y >= (unsigned)RESX) continue;
#pragma unroll
        for (int kj = 0; kj < 3; kj++) {
            int x = w + 1 - kj;
            if ((unsigned)x >= (unsigned)RESX) continue;
            int a = argb[y * RESX + x];
            int ar = a >> 6, ac = a & 63;
            const float* src = f0b + ((size_t)(ar + ki) * PWD + ac + kj) * CH;
            acc0 += src[lane];
            acc1 += src[lane + 32];
        }
    }
    float* Tout = g_concat + ((size_t)b * 2 * CH + CH) * HW + l;
    Tout[(size_t)lane * HW] = acc0 * (1.f / 9.f);
    Tout[(size_t)(lane + 32) * HW] = acc1 * (1.f / 9.f);
}

// Direct conv, 64 out channels, tile = 1 row (64px) x 64 cout; thread = 2px x 8cout.
// f32x2: accumulators paired over cout (weight pairs free from contiguous smem).
template <int KS, int CIN, bool RELU, bool HASRES>
__global__ void __launch_bounds__(256) conv_kernel(const float* __restrict__ in, int inBS,
                                                   const float* __restrict__ wt,
                                                   const float* __restrict__ bias,
                                                   const float* __restrict__ res,
                                                   float* __restrict__ out, int outBS) {
    constexpr int PAD = KS / 2;
    constexpr int IW = 64 + 2 * PAD;
    constexpr int K2 = KS * KS;
    __shared__ __align__(16) float sw[K2 * 64];
    __shared__ __align__(16) float sin_[KS][IW];
    const int b = blockIdx.y;
    const int row = blockIdx.x;
    const int t = threadIdx.x;
    const int og = t & 7, pg = t >> 3;
    const int c0 = pg * 2;
    unsigned long long acc2[2][4];
#pragma unroll
    for (int i = 0; i < 2; i++)
#pragma unroll
        for (int j = 0; j < 4; j++) acc2[i][j] = 0ULL;

    const float* inb = in + (size_t)b * inBS;
    for (int ci = 0; ci < CIN; ci++) {
        for (int i = t; i < K2 * 64; i += 256) sw[i] = wt[(size_t)ci * K2 * 64 + i];
        for (int i = t; i < KS * IW; i += 256) {
            int r = i / IW, c = i % IW;
            int y = row - PAD + r, x = c - PAD;
            float v = 0.f;
            if ((unsigned)y < 64u && (unsigned)x < 64u)
                v = inb[(size_t)ci * HW + y * 64 + x];
            sin_[r][c] = v;
        }
        __syncthreads();
#pragma unroll
        for (int ky = 0; ky < KS; ky++) {
#pragma unroll
            for (int kx = 0; kx < KS; kx++) {
                float i0 = sin_[ky][c0 + kx];
                float i1 = sin_[ky][c0 + kx + 1];
                unsigned long long i0d = pack2(i0, i0);
                unsigned long long i1d = pack2(i1, i1);
                const float* wp = &sw[(ky * KS + kx) * 64 + og * 8];
                ulonglong2 w01 = *(const ulonglong2*)wp;        // (w0,w1),(w2,w3)
                ulonglong2 w23 = *(const ulonglong2*)(wp + 4);  // (w4,w5),(w6,w7)
                ffma2(acc2[0][0], i0d, w01.x);
                ffma2(acc2[0][1], i0d, w01.y);
                ffma2(acc2[0][2], i0d, w23.x);
                ffma2(acc2[0][3], i0d, w23.y);
                ffma2(acc2[1][0], i1d, w01.x);
                ffma2(acc2[1][1], i1d, w01.y);
                ffma2(acc2[1][2], i1d, w23.x);
                ffma2(acc2[1][3], i1d, w23.y);
            }
        }
        __syncthreads();
    }
    float* outb = out + (size_t)b * outBS;
    const float* resb = res + (size_t)b * CH * HW;
#pragma unroll
    for (int jp = 0; jp < 4; jp++) {
        int coA = og * 8 + jp * 2;
#pragma unroll
        for (int i = 0; i < 2; i++) {
            float2 pr = unpack2(acc2[i][jp]);
            float va = pr.x + bias[coA];
            float vb = pr.y + bias[coA + 1];
            if (RELU) { va = fmaxf(va, 0.f); vb = fmaxf(vb, 0.f); }
            size_t ia = (size_t)coA * HW + row * 64 + c0 + i;
            size_t ib = ia + HW;
            if (HASRES) { va += resb[ia]; vb += resb[ib]; }
            outb[ia] = va;
            outb[ib] = vb;
        }
    }
}

// out[b][l][c] = fea[b][c][l] + xs[b][c][l] * S[b][l]  (transpose via smem)
__global__ void __launch_bounds__(256) finalize_kernel(float* __restrict__ out) {
    __shared__ float s[64][65];
    const int b = blockIdx.y, lr = blockIdx.x;
    const float* fea = g_concat + (size_t)b * 2 * CH * HW;
    const float* xs = g_xs + (size_t)b * CH * HW;
    const float* Sv = g_Rstar + b * HW + lr * 64;
    for (int i = threadIdx.x; i < 64 * 64; i += 256) {
        int ch = i >> 6, lc = i & 63;
        size_t idx = (size_t)ch * HW + lr * 64 + lc;
        s[lc][ch] = fea[idx] + xs[idx] * Sv[lc];
    }
    __syncthreads();
    float* ob = out + ((size_t)b * HW + (size_t)lr * 64) * 64;
    for (int i = threadIdx.x; i < 64 * 64; i += 256) ob[i] = s[i >> 6][i & 63];
}

// ---------------- host ----------------
static inline float* symaddr(const void* sym) {
    void* p = nullptr;
    cudaGetSymbolAddress(&p, sym);
    return (float*)p;
}

extern "C" void kernel_launch(void* const* d_in, const int* in_sizes, int n_in,
                              void* d_out, int out_size) {
    const float* c0 = (const float*)d_in[0];
    const float* f0 = (const float*)d_in[1];
    const float* c1 = (const float*)d_in[2];
    const float* head_w = (const float*)d_in[3];
    const float* head_b = (const float*)d_in[4];
    const float* rb_w1 = (const float*)d_in[5];
    const float* rb_b1 = (const float*)d_in[6];
    const float* rb_w2 = (const float*)d_in[7];
    const float* rb_b2 = (const float*)d_in[8];
    const float* tail_w = (const float*)d_in[9];
    const float* tail_b = (const float*)d_in[10];
    const float* sq_w = (const float*)d_in[11];
    const float* sq_b = (const float*)d_in[12];
    float* out = (float*)d_out;

    float* p_delta = symaddr(g_delta);
    float* p_x1 = symaddr(g_x1);
    float* p_hb = symaddr(g_hb);
    float* p_xl = symaddr(g_xl);
    float* p_concat = symaddr(g_concat);
    float* p_xs = symaddr(g_xs);
    float* p_wh = symaddr(g_wt_head);
    float* p_w1 = symaddr(g_wt_rb1);
    float* p_w2 = symaddr(g_wt_rb2);
    float* p_wt = symaddr(g_wt_tail);
    float* p_ws = symaddr(g_wt_sq);

    cudaFuncSetAttribute(dgemm_kernel, cudaFuncAttributeMaxDynamicSharedMemorySize, 65536);

    // launch 0-4: setup; launch 5 = head conv (ncu capture slot)
    zero_all_kernel<<<(BATCH * CH * PP + 255) / 256, 256>>>();
    wtrans_all_kernel<<<(483328 + 255) / 256, 256>>>(
        head_w, rb_w1 + 3 * 36864, rb_w2 + 3 * 36864, tail_w, sq_w);
    pack_kernel<<<dim3(64, BATCH), 256>>>(c0, c1, f0);
    sumsq_kernel<<<BATCH * HW / 8, 256>>>(c0, c1);
    norminv_kernel<<<BATCH * HW / 256, 256>>>();

    // conv stack prefix (only residual block 3 is live in the reference)
    conv_kernel<5, 64, false, false><<<dim3(64, BATCH), 256>>>(
        p_delta, CH * HW, p_wh, head_b, nullptr, p_x1, CH * HW);
    conv_kernel<3, 64, true, false><<<dim3(64, BATCH), 256>>>(
        p_x1, CH * HW, p_w1, rb_b1 + 3 * 64, nullptr, p_hb, CH * HW);
    conv_kernel<3, 64, false, true><<<dim3(64, BATCH), 256>>>(
        p_hb, CH * HW, p_w2, rb_b2 + 3 * 64, p_x1, p_xl, CH * HW);
    conv_kernel<5, 64, false, true><<<dim3(64, BATCH), 256>>>(
        p_xl, CH * HW, p_wt, tail_b, p_x1, p_concat, 2 * CH * HW);  // -> concat[0:64]

    // patch-correlation search
    for (int b = 0; b < BATCH; b++) {
        dgemm_kernel<<<dim3(35, 35), 256, 65536>>>(b);
        assemble_kernel<<<dim3(64, 4), 256>>>(b);
        merge_kernel<<<HW / 256, 256>>>(b);
    }
    gather_kernel<<<BATCH * HW / 8, 256>>>();

    conv_kernel<5, 128, false, false><<<dim3(64, BATCH), 256>>>(
        p_concat, 2 * CH * HW, p_ws, sq_b, nullptr, p_xs, CH * HW);

    finalize_kernel<<<dim3(64, BATCH), 256>>>(out);
}

// round 7
// speedup vs baseline: 1.7382x; 1.7248x over previous
#include <cuda_runtime.h>
#include <cuda_bf16.h>
#include <math.h>
#include <stdint.h>

#define CH 64
#define RESX 64
#define HW 4096
#define PWD 66
#define PP 4356
#define BATCH 4

// ---------------- helpers ----------------
__device__ __forceinline__ unsigned long long pack2(float lo, float hi) {
    unsigned long long r;
    asm("mov.b64 %0, {%1, %2};" : "=l"(r) : "f"(lo), "f"(hi));
    return r;
}
__device__ __forceinline__ void ffma2(unsigned long long& d, unsigned long long a,
                                      unsigned long long b) {
    asm("fma.rn.f32x2 %0, %1, %2, %0;" : "+l"(d) : "l"(a), "l"(b));
}

// warp mma m16n8k16 row.col bf16 -> f32
__device__ __forceinline__ void hmma(float* d, const uint32_t* a, const uint32_t* b) {
    asm volatile(
        "mma.sync.aligned.m16n8k16.row.col.f32.bf16.bf16.f32 "
        "{%0,%1,%2,%3}, {%4,%5,%6,%7}, {%8,%9}, {%0,%1,%2,%3};"
        : "+f"(d[0]), "+f"(d[1]), "+f"(d[2]), "+f"(d[3])
        : "r"(a[0]), "r"(a[1]), "r"(a[2]), "r"(a[3]), "r"(b[0]), "r"(b[1]));
}

// ---------------- static device scratch ----------------
__device__ float g_c0p[BATCH * CH * PP];
__device__ float g_c1p[BATCH * CH * PP];
__device__ float g_f0pl[BATCH * PP * CH];
__device__ float g_delta[BATCH * CH * HW];
__device__ float g_s0[BATCH * PP];
__device__ float g_s1[BATCH * PP];
__device__ float g_inv0[BATCH * HW];
__device__ float g_inv1[BATCH * HW];
__device__ float g_D[(size_t)PP * PP];        // 75.9 MB, per-batch reuse (L2 resident)
__device__ float g_pval[16 * HW];
__device__ int   g_parg[16 * HW];
__device__ float g_Rstar[BATCH * HW];
__device__ int   g_Rarg[BATCH * HW];
__device__ float g_x1[BATCH * CH * HW];
__device__ float g_hb[BATCH * CH * HW];
__device__ float g_xl[BATCH * CH * HW];
__device__ float g_concat[BATCH * 2 * CH * HW];
__device__ float g_xs[BATCH * CH * HW];
// bf16 split weights, original [co][k] (OIHW flat) layout, concatenated
#define WOFF_HEAD 0
#define WOFF_RB1 102400
#define WOFF_RB2 139264
#define WOFF_TAIL 176128
#define WOFF_SQ 278528
#define WTOT 483328
__device__ __nv_bfloat16 g_wbf_hi[WTOT];
__device__ __nv_bfloat16 g_wbf_lo[WTOT];

// ---------------- setup kernels ----------------
__global__ void zero_all_kernel() {
    int i = blockIdx.x * 256 + threadIdx.x;
    const int N1 = BATCH * CH * PP;
    if (i < N1) {
        g_c0p[i] = 0.f;
        g_c1p[i] = 0.f;
        g_f0pl[i] = 0.f;
    }
    if (i < BATCH * PP) {
        g_s0[i] = 0.f;
        g_s1[i] = 0.f;
    }
}

__global__ void wconv_all_kernel(const float* __restrict__ hw, const float* __restrict__ w1,
                                 const float* __restrict__ w2, const float* __restrict__ tw,
                                 const float* __restrict__ sw) {
    int i = blockIdx.x * 256 + threadIdx.x;
    if (i >= WTOT) return;
    float v;
    if (i < WOFF_RB1) v = hw[i];
    else if (i < WOFF_RB2) v = w1[i - WOFF_RB1];
    else if (i < WOFF_TAIL) v = w2[i - WOFF_RB2];
    else if (i < WOFF_SQ) v = tw[i - WOFF_TAIL];
    else v = sw[i - WOFF_SQ];
    __nv_bfloat16 h = __float2bfloat16(v);
    g_wbf_hi[i] = h;
    g_wbf_lo[i] = __float2bfloat16(v - __bfloat162float(h));
}

__global__ void __launch_bounds__(256) pack_kernel(const float* __restrict__ c0,
                                                   const float* __restrict__ c1,
                                                   const float* __restrict__ f0) {
    __shared__ float s0[64][65];
    __shared__ float s1[64][65];
    const int b = blockIdx.y, lr = blockIdx.x;
    const float* c0row = c0 + ((size_t)b * HW + (size_t)lr * 64) * CH;
    const float* c1row = c1 + ((size_t)b * HW + (size_t)lr * 64) * CH;
    const float* f0row = f0 + ((size_t)b * HW + (size_t)lr * 64) * CH;
    float* f0dst = g_f0pl + ((size_t)b * PP + (size_t)(lr + 1) * PWD + 1) * CH;
    for (int i = threadIdx.x; i < 64 * 64; i += 256) {
        int lc = i >> 6, ch = i & 63;
        s0[lc][ch] = c0row[i];
        s1[lc][ch] = c1row[i];
        f0dst[i] = f0row[i];
    }
    __syncthreads();
    const size_t pbase = (size_t)b * CH * PP;
    const int prow = (lr + 1) * PWD + 1;
    for (int i = threadIdx.x; i < 64 * 64; i += 256) {
        int ch = i >> 6, lc = i & 63;
        float v0 = s0[lc][ch], v1 = s1[lc][ch];
        g_c0p[pbase + (size_t)ch * PP + prow + lc] = v0;
        g_c1p[pbase + (size_t)ch * PP + prow + lc] = v1;
        g_delta[(size_t)b * CH * HW + (size_t)ch * HW + lr * 64 + lc] = v1 - v0;
    }
}

__global__ void sumsq_kernel(const float* __restrict__ c0, const float* __restrict__ c1) {
    int gw = blockIdx.x * 8 + (threadIdx.x >> 5);
    int lane = threadIdx.x & 31;
    int b = gw >> 12, l = gw & 4095;
    const float* p0 = c0 + ((size_t)b * HW + l) * CH;
    const float* p1 = c1 + ((size_t)b * HW + l) * CH;
    float a = p0[lane], a2 = p0[lane + 32];
    float s0 = a * a + a2 * a2;
    float bb = p1[lane], b2 = p1[lane + 32];
    float s1 = bb * bb + b2 * b2;
#pragma unroll
    for (int off = 16; off; off >>= 1) {
        s0 += __shfl_down_sync(0xffffffffu, s0, off);
        s1 += __shfl_down_sync(0xffffffffu, s1, off);
    }
    if (lane == 0) {
        int pr = ((l >> 6) + 1) * PWD + (l & 63) + 1;
        g_s0[b * PP + pr] = s0;
        g_s1[b * PP + pr] = s1;
    }
}

__global__ void norminv_kernel() {
    int i = blockIdx.x * 256 + threadIdx.x;
    if (i >= BATCH * HW) return;
    int b = i >> 12, l = i & 4095;
    int lp = (l >> 6) * PWD + (l & 63);
    float t0 = 0.f, t1 = 0.f;
#pragma unroll
    for (int ki = 0; ki < 3; ki++)
#pragma unroll
        for (int kj = 0; kj < 3; kj++) {
            int p = lp + ki * PWD + kj;
            t0 += g_s0[b * PP + p];
            t1 += g_s1[b * PP + p];
        }
    g_inv0[i] = 1.f / fmaxf(sqrtf(t0), 1e-12f);
    g_inv1[i] = 1.f / fmaxf(sqrtf(t1), 1e-12f);
}

// ---------------- search path (fp32, unchanged from passing R4) ----------------
__global__ void __launch_bounds__(256) dgemm_kernel(int b) {
    extern __shared__ __align__(16) float sm[];
    float* As = sm;
    float* Bs = sm + 64 * 128;
    const float* A = g_c0p + (size_t)b * CH * PP;
    const float* Bm = g_c1p + (size_t)b * CH * PP;
    const int p0 = blockIdx.y * 128, q0 = blockIdx.x * 128;
    for (int i = threadIdx.x * 4; i < 64 * 128; i += 1024) {
        int k = i >> 7, x = i & 127;
        float4 va = make_float4(0.f, 0.f, 0.f, 0.f);
        float4 vb = va;
        if (p0 + x < PP) va = *(const float4*)&A[(size_t)k * PP + p0 + x];
        if (q0 + x < PP) vb = *(const float4*)&Bm[(size_t)k * PP + q0 + x];
        *(float4*)&As[k * 128 + x] = va;
        *(float4*)&Bs[k * 128 + x] = vb;
    }
    __syncthreads();
    const int ty = threadIdx.x >> 4, tx = threadIdx.x & 15;
    unsigned long long acc[8][4];
#pragma unroll
    for (int p = 0; p < 8; p++)
#pragma unroll
        for (int j = 0; j < 4; j++) acc[p][j] = 0ULL;
    const float* ap = &As[ty * 8];
    const float* bp = &Bs[tx * 8];
#pragma unroll 16
    for (int k = 0; k < 64; k++) {
        float4 a0 = *(const float4*)(ap + k * 128);
        float4 a1 = *(const float4*)(ap + k * 128 + 4);
        ulonglong2 b01 = *(const ulonglong2*)(bp + k * 128);
        ulonglong2 b23 = *(const ulonglong2*)(bp + k * 128 + 4);
        float av[8] = {a0.x, a0.y, a0.z, a0.w, a1.x, a1.y, a1.z, a1.w};
#pragma unroll
        for (int p = 0; p < 8; p++) {
            unsigned long long ad = pack2(av[p], av[p]);
            ffma2(acc[p][0], ad, b01.x);
            ffma2(acc[p][1], ad, b01.y);
            ffma2(acc[p][2], ad, b23.x);
            ffma2(acc[p][3], ad, b23.y);
        }
    }
    const int qb = q0 + tx * 8;
#pragma unroll
    for (int p = 0; p < 8; p++) {
        int gp = p0 + ty * 8 + p;
        if (gp < PP) {
            float* drow = &g_D[(size_t)gp * PP];
            if (qb + 3 < PP)
                *(ulonglong2*)&drow[qb] = make_ulonglong2(acc[p][0], acc[p][1]);
            if (qb + 7 < PP)
                *(ulonglong2*)&drow[qb + 4] = make_ulonglong2(acc[p][2], acc[p][3]);
        }
    }
}

__global__ void __launch_bounds__(256) assemble_kernel(int b) {
    const int mi = threadIdx.x & 63;
    const int sub = threadIdx.x >> 6;
    const int mr = blockIdx.x;
    const int m = mr * 64 + mi;
    const int mp = mr * PWD + mi;
    const int chunk = blockIdx.y * 4 + sub;
    const int l0 = chunk * 256;
    const float* inv0 = g_inv0 + b * HW;
    float best = -1e30f;
    int barg = 0;
    for (int li = 0; li < 256; li++) {
        int l = l0 + li;
        int lr = l >> 6, lc = l & 63;
        size_t lp = (size_t)lr * PWD + lc;
        float dot = 0.f;
#pragma unroll
        for (int ki = 0; ki < 3; ki++)
#pragma unroll
            for (int kj = 0; kj < 3; kj++) {
                size_t o = (size_t)ki * PWD + kj;
                dot += __ldg(&g_D[(lp + o) * PP + mp + o]);
            }
        float v = dot * __ldg(&inv0[l]);
        if (v > best) { best = v; barg = l; }
    }
    g_pval[chunk * HW + m] = best;
    g_parg[chunk * HW + m] = barg;
}

__global__ void merge_kernel(int b) {
    int m = blockIdx.x * 256 + threadIdx.x;
    if (m >= HW) return;
    float best = -1e30f;
    int barg = 0;
#pragma unroll
    for (int c = 0; c < 16; c++) {
        float v = g_pval[c * HW + m];
        if (v > best) { best = v; barg = g_parg[c * HW + m]; }
    }
    g_Rstar[b * HW + m] = best * g_inv1[b * HW + m];
    g_Rarg[b * HW + m] = barg;
}

__global__ void gather_kernel() {
    int gw = blockIdx.x * 8 + (threadIdx.x >> 5);
    int lane = threadIdx.x & 31;
    int b = gw >> 12, l = gw & 4095;
    int h = l >> 6, w = l & 63;
    const float* f0b = g_f0pl + (size_t)b * PP * CH;
    const int* argb = g_Rarg + b * HW;
    float acc0 = 0.f, acc1 = 0.f;
#pragma unroll
    for (int ki = 0; ki < 3; ki++) {
        int y = h + 1 - ki;
        if ((unsigned)y >= (unsigned)RESX) continue;
#pragma unroll
        for (int kj = 0; kj < 3; kj++) {
            int x = w + 1 - kj;
            if ((unsigned)x >= (unsigned)RESX) continue;
            int a = argb[y * RESX + x];
            int ar = a >> 6, ac = a & 63;
            const float* src = f0b + ((size_t)(ar + ki) * PWD + ac + kj) * CH;
            acc0 += src[lane];
            acc1 += src[lane + 32];
        }
    }
    float* Tout = g_concat + ((size_t)b * 2 * CH + CH) * HW + l;
    Tout[(size_t)lane * HW] = acc0 * (1.f / 9.f);
    Tout[(size_t)(lane + 32) * HW] = acc1 * (1.f / 9.f);
}

// ---------------- HMMA bf16-split conv ----------------
// D[128 pix, 64 cout] = sum_k im2col[pix,k] * W[cout,k], 3-term bf16 split in fp32.
// 8 warps: warp (wid&3) -> 32-row band, (wid>>2) -> 32-col band; 2x4 m16n8 tiles.
// smem: Ah[128][72] bf16 @0, Al @18432, Bh[64][72] @36864, Bl @46080; total 55296.
// Epilogue reuses smem as S[64][132] f32 transpose buffer.
#define CAH 0
#define CAL 18432
#define CBH 36864
#define CBL 46080
#define CSM_TOTAL 55296
#define ASTRIDE 72
#define BSTRIDE 72

template <int KS, int CIN, bool RELU, bool HASRES>
__global__ void __launch_bounds__(256) conv_hmma_kernel(
    const float* __restrict__ in, int inBS,
    const __nv_bfloat16* __restrict__ whi, const __nv_bfloat16* __restrict__ wlo,
    const float* __restrict__ bias, const float* __restrict__ res,
    float* __restrict__ out, int outBS) {
    constexpr int K2 = KS * KS;
    constexpr int K = CIN * K2;
    constexpr int NSLAB = K / 64;
    constexpr int PAD = KS / 2;
    static_assert(K % 64 == 0, "K must be multiple of 64");

    extern __shared__ __align__(16) char smem[];
    __nv_bfloat16* Ah = (__nv_bfloat16*)(smem + CAH);
    __nv_bfloat16* Al = (__nv_bfloat16*)(smem + CAL);
    __nv_bfloat16* Bh = (__nv_bfloat16*)(smem + CBH);
    __nv_bfloat16* Bl = (__nv_bfloat16*)(smem + CBL);

    const int tid = threadIdx.x;
    const int wid = tid >> 5, lane = tid & 31;
    const int b = blockIdx.y;
    const int py0 = blockIdx.x * 2;   // 128-pixel tile = 2 image rows
    const int g = lane >> 2, tg = lane & 3;

    const float* inb = in + (size_t)b * inBS;

    float d[2][4][4];
#pragma unroll
    for (int mt = 0; mt < 2; mt++)
#pragma unroll
        for (int nt = 0; nt < 4; nt++)
#pragma unroll
            for (int r = 0; r < 4; r++) d[mt][nt][r] = 0.f;

    const int mrow = (wid & 3) * 32;
    const int ncol = (wid >> 2) * 32;

    for (int s = 0; s < NSLAB; s++) {
        // fill A im2col (hi/lo), 128 px x 64 k
        for (int i = tid; i < 128 * 32; i += 256) {
            int p = i >> 5;
            int kk = (i & 31) * 2;
            int py = py0 + (p >> 6), px = p & 63;
            uint32_t hpack = 0, lpack = 0;
#pragma unroll
            for (int u = 0; u < 2; u++) {
                int k = s * 64 + kk + u;
                int ci = k / K2;
                int t = k - ci * K2;
                int ky = t / KS, kx = t - ky * KS;
                int y = py + ky - PAD, x = px + kx - PAD;
                float v = 0.f;
                if ((unsigned)y < 64u && (unsigned)x < 64u)
                    v = inb[(size_t)ci * HW + y * 64 + x];
                __nv_bfloat16 h = __float2bfloat16(v);
                __nv_bfloat16 lo = __float2bfloat16(v - __bfloat162float(h));
                hpack |= (uint32_t)__bfloat16_as_ushort(h) << (u * 16);
                lpack |= (uint32_t)__bfloat16_as_ushort(lo) << (u * 16);
            }
            *(uint32_t*)&Ah[p * ASTRIDE + kk] = hpack;
            *(uint32_t*)&Al[p * ASTRIDE + kk] = lpack;
        }
        // fill B weights (hi/lo), 64 co x 64 k
        for (int i = tid; i < 64 * 32; i += 256) {
            int co = i >> 5;
            int kk = (i & 31) * 2;
            size_t gk = (size_t)co * K + s * 64 + kk;
            uint32_t hpack = ((uint32_t)__bfloat16_as_ushort(whi[gk])) |
                             ((uint32_t)__bfloat16_as_ushort(whi[gk + 1]) << 16);
            uint32_t lpack = ((uint32_t)__bfloat16_as_ushort(wlo[gk])) |
                             ((uint32_t)__bfloat16_as_ushort(wlo[gk + 1]) << 16);
            *(uint32_t*)&Bh[co * BSTRIDE + kk] = hpack;
            *(uint32_t*)&Bl[co * BSTRIDE + kk] = lpack;
        }
        __syncthreads();

#pragma unroll
        for (int ks16 = 0; ks16 < 4; ks16++) {
            const int kb = ks16 * 16;
            uint32_t ah[2][4], al[2][4], bh[4][2], bl[4][2];
#pragma unroll
            for (int mt = 0; mt < 2; mt++) {
                int r0 = mrow + mt * 16 + g;
                int c0 = kb + tg * 2;
                ah[mt][0] = *(const uint32_t*)&Ah[r0 * ASTRIDE + c0];
                ah[mt][1] = *(const uint32_t*)&Ah[(r0 + 8) * ASTRIDE + c0];
                ah[mt][2] = *(const uint32_t*)&Ah[r0 * ASTRIDE + c0 + 8];
                ah[mt][3] = *(const uint32_t*)&Ah[(r0 + 8) * ASTRIDE + c0 + 8];
                al[mt][0] = *(const uint32_t*)&Al[r0 * ASTRIDE + c0];
                al[mt][1] = *(const uint32_t*)&Al[(r0 + 8) * ASTRIDE + c0];
                al[mt][2] = *(const uint32_t*)&Al[r0 * ASTRIDE + c0 + 8];
                al[mt][3] = *(const uint32_t*)&Al[(r0 + 8) * ASTRIDE + c0 + 8];
            }
#pragma unroll
            for (int nt = 0; nt < 4; nt++) {
                int n = ncol + nt * 8 + g;
                int k0 = kb + tg * 2;
                bh[nt][0] = *(const uint32_t*)&Bh[n * BSTRIDE + k0];
                bh[nt][1] = *(const uint32_t*)&Bh[n * BSTRIDE + k0 + 8];
                bl[nt][0] = *(const uint32_t*)&Bl[n * BSTRIDE + k0];
                bl[nt][1] = *(const uint32_t*)&Bl[n * BSTRIDE + k0 + 8];
            }
#pragma unroll
            for (int mt = 0; mt < 2; mt++)
#pragma unroll
                for (int nt = 0; nt < 4; nt++) {
                    hmma(d[mt][nt], ah[mt], bh[nt]);
                    hmma(d[mt][nt], ah[mt], bl[nt]);
                    hmma(d[mt][nt], al[mt], bh[nt]);
                }
        }
        __syncthreads();
    }

    // epilogue: transpose through smem, coalesced store
    float* S = (float*)smem;   // [64 co][132]
#pragma unroll
    for (int mt = 0; mt < 2; mt++)
#pragma unroll
        for (int nt = 0; nt < 4; nt++) {
            int r0 = mrow + mt * 16 + g;
            int c0 = ncol + nt * 8 + tg * 2;
            S[c0 * 132 + r0] = d[mt][nt][0];
            S[(c0 + 1) * 132 + r0] = d[mt][nt][1];
            S[c0 * 132 + r0 + 8] = d[mt][nt][2];
            S[(c0 + 1) * 132 + r0 + 8] = d[mt][nt][3];
        }
    __syncthreads();
    float* outb = out + (size_t)b * outBS;
    const float* resb = res + (size_t)b * CH * HW;
    const int pix0 = blockIdx.x * 128;
    for (int i = tid; i < 64 * 128; i += 256) {
        int co = i >> 7, pix = i & 127;
        float v = S[co * 132 + pix] + bias[co];
        if (RELU) v = fmaxf(v, 0.f);
        size_t idx = (size_t)co * HW + pix0 + pix;
        if (HASRES) v += resb[idx];
        outb[idx] = v;
    }
}

// out[b][l][c] = fea[b][c][l] + xs[b][c][l] * S[b][l]
__global__ void __launch_bounds__(256) finalize_kernel(float* __restrict__ out) {
    __shared__ float s[64][65];
    const int b = blockIdx.y, lr = blockIdx.x;
    const float* fea = g_concat + (size_t)b * 2 * CH * HW;
    const float* xs = g_xs + (size_t)b * CH * HW;
    const float* Sv = g_Rstar + b * HW + lr * 64;
    for (int i = threadIdx.x; i < 64 * 64; i += 256) {
        int ch = i >> 6, lc = i & 63;
        size_t idx = (size_t)ch * HW + lr * 64 + lc;
        s[lc][ch] = fea[idx] + xs[idx] * Sv[lc];
    }
    __syncthreads();
    float* ob = out + ((size_t)b * HW + (size_t)lr * 64) * 64;
    for (int i = threadIdx.x; i < 64 * 64; i += 256) ob[i] = s[i >> 6][i & 63];
}

// ---------------- host ----------------
static inline float* symaddr(const void* sym) {
    void* p = nullptr;
    cudaGetSymbolAddress(&p, sym);
    return (float*)p;
}

extern "C" void kernel_launch(void* const* d_in, const int* in_sizes, int n_in,
                              void* d_out, int out_size) {
    const float* c0 = (const float*)d_in[0];
    const float* f0 = (const float*)d_in[1];
    const float* c1 = (const float*)d_in[2];
    const float* head_w = (const float*)d_in[3];
    const float* head_b = (const float*)d_in[4];
    const float* rb_w1 = (const float*)d_in[5];
    const float* rb_b1 = (const float*)d_in[6];
    const float* rb_w2 = (const float*)d_in[7];
    const float* rb_b2 = (const float*)d_in[8];
    const float* tail_w = (const float*)d_in[9];
    const float* tail_b = (const float*)d_in[10];
    const float* sq_w = (const float*)d_in[11];
    const float* sq_b = (const float*)d_in[12];
    float* out = (float*)d_out;

    float* p_delta = symaddr(g_delta);
    float* p_x1 = symaddr(g_x1);
    float* p_hb = symaddr(g_hb);
    float* p_xl = symaddr(g_xl);
    float* p_concat = symaddr(g_concat);
    float* p_xs = symaddr(g_xs);
    __nv_bfloat16* p_whi = (__nv_bfloat16*)symaddr(g_wbf_hi);
    __nv_bfloat16* p_wlo = (__nv_bfloat16*)symaddr(g_wbf_lo);

    cudaFuncSetAttribute(dgemm_kernel, cudaFuncAttributeMaxDynamicSharedMemorySize, 65536);
    cudaFuncSetAttribute(conv_hmma_kernel<5, 64, false, false>,
                         cudaFuncAttributeMaxDynamicSharedMemorySize, CSM_TOTAL);
    cudaFuncSetAttribute(conv_hmma_kernel<3, 64, true, false>,
                         cudaFuncAttributeMaxDynamicSharedMemorySize, CSM_TOTAL);
    cudaFuncSetAttribute(conv_hmma_kernel<3, 64, false, true>,
                         cudaFuncAttributeMaxDynamicSharedMemorySize, CSM_TOTAL);
    cudaFuncSetAttribute(conv_hmma_kernel<5, 64, false, true>,
                         cudaFuncAttributeMaxDynamicSharedMemorySize, CSM_TOTAL);
    cudaFuncSetAttribute(conv_hmma_kernel<5, 128, false, false>,
                         cudaFuncAttributeMaxDynamicSharedMemorySize, CSM_TOTAL);

    zero_all_kernel<<<(BATCH * CH * PP + 255) / 256, 256>>>();                       // 0
    wconv_all_kernel<<<(WTOT + 255) / 256, 256>>>(
        head_w, rb_w1 + 3 * 36864, rb_w2 + 3 * 36864, tail_w, sq_w);                 // 1
    pack_kernel<<<dim3(64, BATCH), 256>>>(c0, c1, f0);                               // 2
    sumsq_kernel<<<BATCH * HW / 8, 256>>>(c0, c1);                                   // 3

    // launch index 4 — ncu capture slot: head conv (K=1600)
    conv_hmma_kernel<5, 64, false, false><<<dim3(32, BATCH), 256, CSM_TOTAL>>>(
        p_delta, CH * HW, p_whi + WOFF_HEAD, p_wlo + WOFF_HEAD, head_b, nullptr,
        p_x1, CH * HW);                                                              // 4

    norminv_kernel<<<BATCH * HW / 256, 256>>>();                                     // 5

    conv_hmma_kernel<3, 64, true, false><<<dim3(32, BATCH), 256, CSM_TOTAL>>>(
        p_x1, CH * HW, p_whi + WOFF_RB1, p_wlo + WOFF_RB1, rb_b1 + 3 * 64, nullptr,
        p_hb, CH * HW);
    conv_hmma_kernel<3, 64, false, true><<<dim3(32, BATCH), 256, CSM_TOTAL>>>(
        p_hb, CH * HW, p_whi + WOFF_RB2, p_wlo + WOFF_RB2, rb_b2 + 3 * 64, p_x1,
        p_xl, CH * HW);
    conv_hmma_kernel<5, 64, false, true><<<dim3(32, BATCH), 256, CSM_TOTAL>>>(
        p_xl, CH * HW, p_whi + WOFF_TAIL, p_wlo + WOFF_TAIL, tail_b, p_x1,
        p_concat, 2 * CH * HW);

    // patch-correlation search (fp32)
    for (int b = 0; b < BATCH; b++) {
        dgemm_kernel<<<dim3(35, 35), 256, 65536>>>(b);
        assemble_kernel<<<dim3(64, 4), 256>>>(b);
        merge_kernel<<<HW / 256, 256>>>(b);
    }
    gather_kernel<<<BATCH * HW / 8, 256>>>();

    conv_hmma_kernel<5, 128, false, false><<<dim3(32, BATCH), 256, CSM_TOTAL>>>(
        p_concat, 2 * CH * HW, p_whi + WOFF_SQ, p_wlo + WOFF_SQ, sq_b, nullptr,
        p_xs, CH * HW);

    finalize_kernel<<<dim3(64, BATCH), 256>>>(out);
}